// round 2
// baseline (speedup 1.0000x reference)
#include <cuda_runtime.h>
#include <math.h>

// Problem constants
#define NB    128     // batch
#define TSTEPS 32     // LSTM steps (Tcap-1)
#define TCAP   33
#define DIM   400     // feature dim
#define HID  1024     // hidden
#define EMB   512     // wordvec dim
#define Z4   4096     // 4*HID
#define VOC 10000
#define LPOS   16     // 4x4 spatial positions

// ---------------- device scratch (no allocations allowed) ----------------
__device__ float g_A[NB * LPOS * HID];      // A[n][l][h]        8 MB
__device__ float g_hin[NB * 2 * HID];       // [h | attn] per n  1 MB
__device__ float g_c[NB * HID];             // cell state
__device__ float g_xWx[TSTEPS * NB * Z4];   // x@Wx, [t][n][j]  64 MB
__device__ float g_z[NB * Z4];              // pre-activation z
__device__ float g_hn[TSTEPS * NB * HID];   // h history [t][n][h] 16 MB

// ---------------- zero the output scalar ----------------
__global__ void zero_out_k(float* o) {
    if (threadIdx.x == 0) o[0] = 0.0f;
}

// ---------------- A = einsum('ndxy,dh->nhxy') + b_proj ; h0 = mean ----------------
// Stored transposed: A[n][l][h]. Also writes h0 into g_hin[:, :HID] and g_c.
__global__ void compute_A_k(const float* __restrict__ features,
                            const float* __restrict__ W_proj,
                            const float* __restrict__ b_proj) {
    __shared__ float fsh[DIM * LPOS];          // 25.6 KB: features[n][d][l]
    const int n   = blockIdx.y;
    const int tid = threadIdx.x;               // 128 threads
    const float* fn = features + n * DIM * LPOS;
    for (int i = tid; i < DIM * LPOS; i += 128) fsh[i] = fn[i];
    __syncthreads();

    const int h = blockIdx.x * 128 + tid;      // 8 h-tiles
    float acc[LPOS];
#pragma unroll
    for (int l = 0; l < LPOS; l++) acc[l] = 0.0f;

    const float4* f4 = (const float4*)fsh;
    for (int d = 0; d < DIM; d++) {
        const float wp = W_proj[d * HID + h];
        const float4 a = f4[d * 4 + 0];
        const float4 b = f4[d * 4 + 1];
        const float4 c = f4[d * 4 + 2];
        const float4 e = f4[d * 4 + 3];
        float fv[LPOS] = {a.x, a.y, a.z, a.w, b.x, b.y, b.z, b.w,
                          c.x, c.y, c.z, c.w, e.x, e.y, e.z, e.w};
#pragma unroll
        for (int l = 0; l < LPOS; l++) acc[l] += fv[l] * wp;
    }

    const float bias = b_proj[h];
    float s = 0.0f;
#pragma unroll
    for (int l = 0; l < LPOS; l++) {
        const float v = acc[l] + bias;
        g_A[n * (LPOS * HID) + l * HID + h] = v;
        s += v;
    }
    const float h0 = s * (1.0f / 16.0f);
    g_hin[n * (2 * HID) + h] = h0;
    g_c[n * HID + h]         = h0;
}

// ---------------- xWx[r][j] = W_embed[tok[r]] @ Wx,  r = t*128+n ----------------
// Tiled 64x64 fp32 GEMM with gathered A rows. M=4096, K=512, N=4096.
__global__ void embed_gemm_k(const int* __restrict__ captions,
                             const float* __restrict__ W_embed,
                             const float* __restrict__ Wx) {
    __shared__ float As[16][64];
    __shared__ float Bs[16][64];
    __shared__ int   tok[64];

    const int tid = threadIdx.x;               // 256
    const int r0 = blockIdx.y * 64;
    const int j0 = blockIdx.x * 64;

    if (tid < 64) {
        const int r = r0 + tid;
        const int t = r >> 7;                  // r = t*128+n
        const int n = r & 127;
        tok[tid] = captions[n * TCAP + t];     // cap_in[:, t]
    }
    __syncthreads();

    const int ty = tid >> 4, tx = tid & 15;
    float acc[4][4];
#pragma unroll
    for (int i = 0; i < 4; i++)
#pragma unroll
        for (int j = 0; j < 4; j++) acc[i][j] = 0.0f;

    for (int k0 = 0; k0 < EMB; k0 += 16) {
#pragma unroll
        for (int i = 0; i < 4; i++) {
            const int idx = tid + i * 256;     // 0..1023
            const int rr = idx >> 4, kk = idx & 15;
            As[kk][rr] = W_embed[tok[rr] * EMB + k0 + kk];
            const int kb = idx >> 6, jj = idx & 63;
            Bs[kb][jj] = Wx[(k0 + kb) * Z4 + j0 + jj];
        }
        __syncthreads();
#pragma unroll
        for (int kk = 0; kk < 16; kk++) {
            const float4 av = *(const float4*)&As[kk][ty * 4];
            const float4 bv = *(const float4*)&Bs[kk][tx * 4];
            const float a_[4] = {av.x, av.y, av.z, av.w};
            const float b_[4] = {bv.x, bv.y, bv.z, bv.w};
#pragma unroll
            for (int i = 0; i < 4; i++)
#pragma unroll
                for (int j = 0; j < 4; j++) acc[i][j] += a_[i] * b_[j];
        }
        __syncthreads();
    }
#pragma unroll
    for (int i = 0; i < 4; i++) {
        const int r = r0 + ty * 4 + i;
        float4 st = make_float4(acc[i][0], acc[i][1], acc[i][2], acc[i][3]);
        *(float4*)&g_xWx[r * Z4 + j0 + tx * 4] = st;
    }
}

// ---------------- attention: w = softmax(h·A_l / sqrt(H)); attn = A @ w ----------------
__global__ void attn_k() {
    __shared__ float e_sh[LPOS];
    __shared__ float w_sh[LPOS];
    const int n    = blockIdx.x;
    const int tid  = threadIdx.x;              // 512 = 16 warps
    const int warp = tid >> 5, lane = tid & 31;
    const float* An = g_A   + n * (LPOS * HID);
    const float* hp = g_hin + n * (2 * HID);   // prev_h

    // e[l]: one warp per l
    float s = 0.0f;
    const float* Al = An + warp * HID;
    for (int h = lane; h < HID; h += 32) s += hp[h] * Al[h];
#pragma unroll
    for (int off = 16; off > 0; off >>= 1) s += __shfl_down_sync(0xFFFFFFFF, s, off);
    if (lane == 0) e_sh[warp] = s * 0.03125f;  // 1/sqrt(1024)
    __syncthreads();

    if (tid == 0) {                            // 16-way softmax, serial is trivial
        float m = -1e30f;
#pragma unroll
        for (int l = 0; l < LPOS; l++) m = fmaxf(m, e_sh[l]);
        float ss = 0.0f;
#pragma unroll
        for (int l = 0; l < LPOS; l++) { float w = expf(e_sh[l] - m); w_sh[l] = w; ss += w; }
        const float inv = 1.0f / ss;
#pragma unroll
        for (int l = 0; l < LPOS; l++) w_sh[l] *= inv;
    }
    __syncthreads();

    for (int h = tid; h < HID; h += 512) {
        float a = 0.0f;
#pragma unroll
        for (int l = 0; l < LPOS; l++) a += An[l * HID + h] * w_sh[l];
        g_hin[n * (2 * HID) + HID + h] = a;    // attn slot
    }
}

// ---------------- z = [h|attn] @ [Wh;Wattn] + xWx[t] + b ----------------
// M=128 (2 tiles), N=4096 (64 tiles), K=2048.
__global__ void step_gemm_k(const float* __restrict__ Wh,
                            const float* __restrict__ Wattn,
                            const float* __restrict__ bvec, int t) {
    __shared__ float As[16][64];
    __shared__ float Bs[16][64];

    const int tid = threadIdx.x;               // 256
    const int n0 = blockIdx.y * 64;
    const int j0 = blockIdx.x * 64;
    const int ty = tid >> 4, tx = tid & 15;

    float acc[4][4];
#pragma unroll
    for (int i = 0; i < 4; i++)
#pragma unroll
        for (int j = 0; j < 4; j++) acc[i][j] = 0.0f;

    for (int k0 = 0; k0 < 2 * HID; k0 += 16) {
#pragma unroll
        for (int i = 0; i < 4; i++) {
            const int idx = tid + i * 256;
            const int rr = idx >> 4, kk = idx & 15;
            As[kk][rr] = g_hin[(n0 + rr) * (2 * HID) + k0 + kk];
            const int kb = idx >> 6, jj = idx & 63;
            const int k = k0 + kb;
            const float* Wrow = (k < HID) ? (Wh + k * Z4) : (Wattn + (k - HID) * Z4);
            Bs[kb][jj] = Wrow[j0 + jj];
        }
        __syncthreads();
#pragma unroll
        for (int kk = 0; kk < 16; kk++) {
            const float4 av = *(const float4*)&As[kk][ty * 4];
            const float4 bv = *(const float4*)&Bs[kk][tx * 4];
            const float a_[4] = {av.x, av.y, av.z, av.w};
            const float b_[4] = {bv.x, bv.y, bv.z, bv.w};
#pragma unroll
            for (int i = 0; i < 4; i++)
#pragma unroll
                for (int j = 0; j < 4; j++) acc[i][j] += a_[i] * b_[j];
        }
        __syncthreads();
    }
    const float4 bb = *(const float4*)&bvec[j0 + tx * 4];
#pragma unroll
    for (int i = 0; i < 4; i++) {
        const int nloc = n0 + ty * 4 + i;
        const float4 xw = *(const float4*)&g_xWx[(t * NB + nloc) * Z4 + j0 + tx * 4];
        float4 st = make_float4(acc[i][0] + xw.x + bb.x, acc[i][1] + xw.y + bb.y,
                                acc[i][2] + xw.z + bb.z, acc[i][3] + xw.w + bb.w);
        *(float4*)&g_z[nloc * Z4 + j0 + tx * 4] = st;
    }
}

// ---------------- LSTM gates ----------------
__global__ void gates_k(int t) {
    const int idx = blockIdx.x * 256 + threadIdx.x;  // 512 blocks -> N*HID
    const int n = idx >> 10;
    const int h = idx & 1023;
    const float* zr = g_z + n * Z4;
    const float ai = zr[h];
    const float af = zr[h + HID];
    const float ao = zr[h + 2 * HID];
    const float ag = zr[h + 3 * HID];
    const float gi = 1.0f / (1.0f + expf(-ai));
    const float gf = 1.0f / (1.0f + expf(-af));
    const float go = 1.0f / (1.0f + expf(-ao));
    const float gg = tanhf(ag);
    const float c  = gf * g_c[idx] + gi * gg;
    const float hh = go * tanhf(c);
    g_c[idx] = c;
    g_hin[n * (2 * HID) + h] = hh;             // next step's prev_h
    g_hn[t * (NB * HID) + idx] = hh;           // history for loss
}

// ---------------- fused vocab GEMM + streaming log-softmax NLL ----------------
// 8 rows x 2 vocab cols per thread. 256 threads cover 512 vocab cols/pass.
// Streaming sum(exp(logit)) without max-tracking: logits here are O(5), far from
// fp32 exp overflow, and per-thread partial sums are ~40 terms (tiny fp error).
#define VROWS 8
__global__ void loss_k(const float* __restrict__ W_vocab,
                       const float* __restrict__ b_vocab,
                       const int* __restrict__ captions,
                       float* __restrict__ out) {
    __shared__ float hs[HID * VROWS];          // [k][8]  32 KB
    __shared__ int   tgt[VROWS];
    const int tid = threadIdx.x;
    const int r0 = blockIdx.x * VROWS;         // 512 blocks cover 4096 rows

    for (int idx = tid; idx < HID * VROWS; idx += 256) {
        const int k = idx >> 3, rr = idx & 7;
        hs[idx] = g_hn[(r0 + rr) * HID + k];
    }
    if (tid < VROWS) {
        const int r = r0 + tid;
        const int t = r >> 7, n = r & 127;
        tgt[tid] = captions[n * TCAP + t + 1]; // cap_out[:, t]
    }
    __syncthreads();

    float sume[VROWS], tlog[VROWS];
#pragma unroll
    for (int rr = 0; rr < VROWS; rr++) { sume[rr] = 0.0f; tlog[rr] = 0.0f; }

    const float4* hs4 = (const float4*)hs;
    for (int vb = 0; vb < VOC; vb += 512) {
        const int v0 = vb + tid;
        const int v1 = vb + 256 + tid;
        const bool val0 = (v0 < VOC);
        const bool val1 = (v1 < VOC);
        const int c0 = val0 ? v0 : (VOC - 1);
        const int c1 = val1 ? v1 : (VOC - 1);
        const float b0 = b_vocab[c0];
        const float b1 = b_vocab[c1];
        float acc0[VROWS], acc1[VROWS];
#pragma unroll
        for (int rr = 0; rr < VROWS; rr++) { acc0[rr] = b0; acc1[rr] = b1; }
        const float* w0 = W_vocab + c0;
        const float* w1 = W_vocab + c1;
#pragma unroll 2
        for (int k = 0; k < HID; k++) {
            const float wv0 = w0[k * VOC];
            const float wv1 = w1[k * VOC];
            const float4 ha = hs4[k * 2];
            const float4 hb = hs4[k * 2 + 1];
            acc0[0] += ha.x * wv0; acc0[1] += ha.y * wv0;
            acc0[2] += ha.z * wv0; acc0[3] += ha.w * wv0;
            acc0[4] += hb.x * wv0; acc0[5] += hb.y * wv0;
            acc0[6] += hb.z * wv0; acc0[7] += hb.w * wv0;
            acc1[0] += ha.x * wv1; acc1[1] += ha.y * wv1;
            acc1[2] += ha.z * wv1; acc1[3] += ha.w * wv1;
            acc1[4] += hb.x * wv1; acc1[5] += hb.y * wv1;
            acc1[6] += hb.z * wv1; acc1[7] += hb.w * wv1;
        }
        if (val0) {
#pragma unroll
            for (int rr = 0; rr < VROWS; rr++) {
                sume[rr] += __expf(acc0[rr]);
                if (v0 == tgt[rr]) tlog[rr] += acc0[rr];
            }
        }
        if (val1) {
#pragma unroll
            for (int rr = 0; rr < VROWS; rr++) {
                sume[rr] += __expf(acc1[rr]);
                if (v1 == tgt[rr]) tlog[rr] += acc1[rr];
            }
        }
    }
    __syncthreads();                           // done reading hs; reuse as reduce buf
#pragma unroll
    for (int rr = 0; rr < VROWS; rr++) {
        hs[rr * 256 + tid]               = sume[rr];
        hs[VROWS * 256 + rr * 256 + tid] = tlog[rr];
    }
    __syncthreads();
    if (tid < VROWS) {
        float s = 0.0f, tl = 0.0f;
        for (int i = 0; i < 256; i++) {
            s  += hs[tid * 256 + i];
            tl += hs[VROWS * 256 + tid * 256 + i];
        }
        if (tgt[tid] != 0) {                   // NULL mask
            atomicAdd(out, (logf(s) - tl) * (1.0f / (float)NB));
        }
    }
}

// ---------------- launcher ----------------
extern "C" void kernel_launch(void* const* d_in, const int* in_sizes, int n_in,
                              void* d_out, int out_size) {
    const float* features = (const float*)d_in[0];
    const int*   captions = (const int*)  d_in[1];
    const float* W_embed  = (const float*)d_in[2];
    const float* W_proj   = (const float*)d_in[3];
    const float* b_proj   = (const float*)d_in[4];
    const float* Wx       = (const float*)d_in[5];
    const float* Wh       = (const float*)d_in[6];
    const float* Wattn    = (const float*)d_in[7];
    const float* bvec     = (const float*)d_in[8];
    const float* W_vocab  = (const float*)d_in[9];
    const float* b_vocab  = (const float*)d_in[10];
    float* out = (float*)d_out;

    zero_out_k<<<1, 32>>>(out);
    compute_A_k<<<dim3(8, NB), 128>>>(features, W_proj, b_proj);
    embed_gemm_k<<<dim3(64, 64), 256>>>(captions, W_embed, Wx);
    for (int t = 0; t < TSTEPS; t++) {
        attn_k<<<NB, 512>>>();
        step_gemm_k<<<dim3(64, 2), 256>>>(Wh, Wattn, bvec, t);
        gates_k<<<512, 256>>>(t);
    }
    loss_k<<<512, 256>>>(W_vocab, b_vocab, captions, out);
}

// round 4
// speedup vs baseline: 3.5477x; 3.5477x over previous
#include <cuda_runtime.h>
#include <cuda_bf16.h>
#include <math.h>
#include <stdint.h>

// Problem constants
#define NB    128
#define TSTEPS 32
#define TCAP   33
#define DIM   400
#define HID  1024
#define EMB   512
#define K2   2048      // 2*HID
#define Z4   4096
#define VOC 10000
#define LPOS   16
#define NROWS (TSTEPS * NB)     // 4096
#define VOCP  10112             // 79 * 128
#define SA 40                   // padded smem stride (bf16 elems): conflict-free ldmatrix

// ---------------- device scratch ----------------
__device__ float g_A[NB * LPOS * HID];
__device__ float g_hin[NB * 2 * HID];              // fp32 [h | attn]
__device__ __nv_bfloat16 g_hinb[NB * K2];          // bf16 [h | attn]
__device__ float g_c[NB * HID];
__device__ float g_xWx[TSTEPS * NB * Z4];
__device__ float g_z[NB * Z4];
__device__ __nv_bfloat16 g_hnb[NROWS * HID];       // bf16 h history
__device__ __nv_bfloat16 g_wvb[VOCP * HID];        // bf16 W_vocab^T [v][k]
__device__ __nv_bfloat16 g_wtb[Z4 * K2];           // bf16 [Wh;Wattn]^T [j][k]
__device__ float g_scores[(size_t)NROWS * VOCP];

// ---------------- mma helpers ----------------
__device__ __forceinline__ uint32_t smem_u32(const void* p) {
    uint32_t a;
    asm("{ .reg .u64 t; cvta.to.shared.u64 t, %1; cvt.u32.u64 %0, t; }" : "=r"(a) : "l"(p));
    return a;
}
__device__ __forceinline__ void ldsm4(uint32_t* r, uint32_t a) {
    asm volatile("ldmatrix.sync.aligned.m8n8.x4.shared.b16 {%0,%1,%2,%3}, [%4];"
        : "=r"(r[0]), "=r"(r[1]), "=r"(r[2]), "=r"(r[3]) : "r"(a));
}
__device__ __forceinline__ void mmabf16(float* d, const uint32_t* a, const uint32_t* b) {
    asm volatile("mma.sync.aligned.m16n8k16.row.col.f32.bf16.bf16.f32 "
        "{%0,%1,%2,%3}, {%4,%5,%6,%7}, {%8,%9}, {%0,%1,%2,%3};"
        : "+f"(d[0]), "+f"(d[1]), "+f"(d[2]), "+f"(d[3])
        : "r"(a[0]), "r"(a[1]), "r"(a[2]), "r"(a[3]), "r"(b[0]), "r"(b[1]));
}

// ---------------- zero out ----------------
__global__ void zero_out_k(float* o) { if (threadIdx.x == 0) o[0] = 0.0f; }

// ---------------- A projection + h0 ----------------
__global__ void compute_A_k(const float* __restrict__ features,
                            const float* __restrict__ W_proj,
                            const float* __restrict__ b_proj) {
    __shared__ float fsh[DIM * LPOS];
    const int n = blockIdx.y, tid = threadIdx.x;
    const float* fn = features + n * DIM * LPOS;
    for (int i = tid; i < DIM * LPOS; i += 128) fsh[i] = fn[i];
    __syncthreads();
    const int h = blockIdx.x * 128 + tid;
    float acc[LPOS];
#pragma unroll
    for (int l = 0; l < LPOS; l++) acc[l] = 0.0f;
    const float4* f4 = (const float4*)fsh;
    for (int d = 0; d < DIM; d++) {
        const float wp = W_proj[d * HID + h];
        const float4 a = f4[d * 4 + 0], b = f4[d * 4 + 1];
        const float4 c = f4[d * 4 + 2], e = f4[d * 4 + 3];
        float fv[LPOS] = {a.x, a.y, a.z, a.w, b.x, b.y, b.z, b.w,
                          c.x, c.y, c.z, c.w, e.x, e.y, e.z, e.w};
#pragma unroll
        for (int l = 0; l < LPOS; l++) acc[l] += fv[l] * wp;
    }
    const float bias = b_proj[h];
    float s = 0.0f;
#pragma unroll
    for (int l = 0; l < LPOS; l++) {
        const float v = acc[l] + bias;
        g_A[n * (LPOS * HID) + l * HID + h] = v;
        s += v;
    }
    const float h0 = s * (1.0f / 16.0f);
    g_hin[n * (2 * HID) + h] = h0;
    g_hinb[n * K2 + h] = __float2bfloat16(h0);
    g_c[n * HID + h] = h0;
}

// ---------------- embed GEMM: xWx = W_embed[tok] @ Wx (fp32) ----------------
__global__ void embed_gemm_k(const int* __restrict__ captions,
                             const float* __restrict__ W_embed,
                             const float* __restrict__ Wx) {
    __shared__ float As[16][64];
    __shared__ float Bs[16][64];
    __shared__ int tok[64];
    const int tid = threadIdx.x;
    const int r0 = blockIdx.y * 64, j0 = blockIdx.x * 64;
    if (tid < 64) {
        const int r = r0 + tid, t = r >> 7, n = r & 127;
        tok[tid] = captions[n * TCAP + t];
    }
    __syncthreads();
    const int ty = tid >> 4, tx = tid & 15;
    float acc[4][4];
#pragma unroll
    for (int i = 0; i < 4; i++)
#pragma unroll
        for (int j = 0; j < 4; j++) acc[i][j] = 0.0f;
    for (int k0 = 0; k0 < EMB; k0 += 16) {
#pragma unroll
        for (int i = 0; i < 4; i++) {
            const int idx = tid + i * 256;
            const int rr = idx >> 4, kk = idx & 15;
            As[kk][rr] = W_embed[tok[rr] * EMB + k0 + kk];
            const int kb = idx >> 6, jj = idx & 63;
            Bs[kb][jj] = Wx[(k0 + kb) * Z4 + j0 + jj];
        }
        __syncthreads();
#pragma unroll
        for (int kk = 0; kk < 16; kk++) {
            const float4 av = *(const float4*)&As[kk][ty * 4];
            const float4 bv = *(const float4*)&Bs[kk][tx * 4];
            const float a_[4] = {av.x, av.y, av.z, av.w};
            const float b_[4] = {bv.x, bv.y, bv.z, bv.w};
#pragma unroll
            for (int i = 0; i < 4; i++)
#pragma unroll
                for (int j = 0; j < 4; j++) acc[i][j] += a_[i] * b_[j];
        }
        __syncthreads();
    }
#pragma unroll
    for (int i = 0; i < 4; i++) {
        const int r = r0 + ty * 4 + i;
        float4 st = make_float4(acc[i][0], acc[i][1], acc[i][2], acc[i][3]);
        *(float4*)&g_xWx[r * Z4 + j0 + tx * 4] = st;
    }
}

// ---------------- attention ----------------
__global__ void attn_k() {
    __shared__ float e_sh[LPOS];
    __shared__ float w_sh[LPOS];
    const int n = blockIdx.x, tid = threadIdx.x;
    const int warp = tid >> 5, lane = tid & 31;
    const float* An = g_A + n * (LPOS * HID);
    const float* hp = g_hin + n * (2 * HID);
    float s = 0.0f;
    const float* Al = An + warp * HID;
    for (int h = lane; h < HID; h += 32) s += hp[h] * Al[h];
#pragma unroll
    for (int off = 16; off > 0; off >>= 1) s += __shfl_down_sync(0xFFFFFFFF, s, off);
    if (lane == 0) e_sh[warp] = s * 0.03125f;
    __syncthreads();
    if (tid == 0) {
        float m = -1e30f;
#pragma unroll
        for (int l = 0; l < LPOS; l++) m = fmaxf(m, e_sh[l]);
        float ss = 0.0f;
#pragma unroll
        for (int l = 0; l < LPOS; l++) { float w = expf(e_sh[l] - m); w_sh[l] = w; ss += w; }
        const float inv = 1.0f / ss;
#pragma unroll
        for (int l = 0; l < LPOS; l++) w_sh[l] *= inv;
    }
    __syncthreads();
    for (int h = tid; h < HID; h += 512) {
        float a = 0.0f;
#pragma unroll
        for (int l = 0; l < LPOS; l++) a += An[l * HID + h] * w_sh[l];
        g_hin[n * (2 * HID) + HID + h] = a;
        g_hinb[n * K2 + HID + h] = __float2bfloat16(a);
    }
}

// ---------------- step GEMM (tensor core): z = hinb @ wtb^T + xWx + b ----------------
// M=128(batch), N=64 per CTA (grid 64), K=2048 in 64 chunks of 32.
__global__ void __launch_bounds__(256) step_mma_k(const float* __restrict__ bvec, int t) {
    __shared__ __nv_bfloat16 sA[128 * SA];
    __shared__ __nv_bfloat16 sB[64 * SA];
    const int tid = threadIdx.x, lane = tid & 31, wid = tid >> 5;
    const int wm = (wid >> 2) * 64, wn = (wid & 3) * 16;
    const int j0 = blockIdx.x * 64;
    const uint32_t sa = smem_u32(sA), sb = smem_u32(sB);

    float acc[4][2][4];
#pragma unroll
    for (int mi = 0; mi < 4; mi++)
#pragma unroll
        for (int ni = 0; ni < 2; ni++)
#pragma unroll
            for (int q = 0; q < 4; q++) acc[mi][ni][q] = 0.0f;

    const uint32_t aRow = lane & 15, aK = (lane >> 4) * 8;
    const uint32_t bRow = (lane & 7) + ((lane >> 4) << 3), bK = ((lane >> 3) & 1) * 8;

    for (int kc = 0; kc < K2; kc += 32) {
        {
            // A: 128x32 (512 uint4), B: 64x32 (256 uint4)
            int q = tid;
            {
                const int row = q >> 2, c4 = q & 3;
                *(uint4*)&sA[row * SA + c4 * 8] =
                    *(const uint4*)&g_hinb[row * K2 + kc + c4 * 8];
                *(uint4*)&sB[row * SA + c4 * 8] =
                    *(const uint4*)&g_wtb[(size_t)(j0 + row) * K2 + kc + c4 * 8];
            }
            q += 256;
            {
                const int row = q >> 2, c4 = q & 3;
                *(uint4*)&sA[row * SA + c4 * 8] =
                    *(const uint4*)&g_hinb[row * K2 + kc + c4 * 8];
            }
        }
        __syncthreads();
#pragma unroll
        for (int ks = 0; ks < 2; ks++) {
            uint32_t a[4][4], b[4];
#pragma unroll
            for (int mi = 0; mi < 4; mi++)
                ldsm4(a[mi], sa + ((wm + mi * 16 + aRow) * SA + ks * 16 + aK) * 2);
            ldsm4(b, sb + ((wn + bRow) * SA + ks * 16 + bK) * 2);
#pragma unroll
            for (int mi = 0; mi < 4; mi++)
#pragma unroll
                for (int ni = 0; ni < 2; ni++)
                    mmabf16(acc[mi][ni], a[mi], &b[ni * 2]);
        }
        __syncthreads();
    }
    const int mBase = wm + (lane >> 2);
    const int nOff = 2 * (lane & 3);
#pragma unroll
    for (int mi = 0; mi < 4; mi++) {
#pragma unroll
        for (int ni = 0; ni < 2; ni++) {
            const int j = j0 + wn + ni * 8 + nOff;
            const float2 bb = *(const float2*)&bvec[j];
            const int m0 = mBase + mi * 16;
            const float2 x0 = *(const float2*)&g_xWx[(t * NB + m0) * Z4 + j];
            const float2 x1 = *(const float2*)&g_xWx[(t * NB + m0 + 8) * Z4 + j];
            float2 p0 = make_float2(acc[mi][ni][0] + x0.x + bb.x, acc[mi][ni][1] + x0.y + bb.y);
            float2 p1 = make_float2(acc[mi][ni][2] + x1.x + bb.x, acc[mi][ni][3] + x1.y + bb.y);
            *(float2*)&g_z[m0 * Z4 + j] = p0;
            *(float2*)&g_z[(m0 + 8) * Z4 + j] = p1;
        }
    }
}

// ---------------- LSTM gates ----------------
__global__ void gates_k(int t) {
    const int idx = blockIdx.x * 256 + threadIdx.x;
    const int n = idx >> 10, h = idx & 1023;
    const float* zr = g_z + n * Z4;
    const float ai = zr[h], af = zr[h + HID], ao = zr[h + 2 * HID], ag = zr[h + 3 * HID];
    const float gi = 1.0f / (1.0f + expf(-ai));
    const float gf = 1.0f / (1.0f + expf(-af));
    const float go = 1.0f / (1.0f + expf(-ao));
    const float gg = tanhf(ag);
    const float c = gf * g_c[idx] + gi * gg;
    const float hh = go * tanhf(c);
    g_c[idx] = c;
    g_hin[n * (2 * HID) + h] = hh;
    g_hinb[n * K2 + h] = __float2bfloat16(hh);
    g_hnb[t * (NB * HID) + idx] = __float2bfloat16(hh);
}

// ---------------- conversions ----------------
// W_vocab [HID][VOC] -> g_wvb [VOCP][HID] bf16, zero-padded
__global__ void conv_wv_k(const float* __restrict__ W_vocab) {
    __shared__ float ts[32][33];
    const int tx = threadIdx.x, ty = threadIdx.y;       // (32, 8)
    const int v0 = blockIdx.x * 32, k0 = blockIdx.y * 32;
    const int v = v0 + tx;
#pragma unroll
    for (int j = 0; j < 4; j++) {
        const int k = k0 + ty + j * 8;
        ts[ty + j * 8][tx] = (v < VOC) ? W_vocab[k * VOC + v] : 0.0f;
    }
    __syncthreads();
#pragma unroll
    for (int j = 0; j < 4; j++) {
        const int vOut = v0 + ty + j * 8;
        const int kOut = k0 + tx;
        g_wvb[vOut * HID + kOut] = __float2bfloat16(ts[tx][ty + j * 8]);
    }
}

// [Wh;Wattn] [K2][Z4] -> g_wtb [Z4][K2] bf16
__global__ void conv_wt_k(const float* __restrict__ Wh,
                          const float* __restrict__ Wattn) {
    __shared__ float ts[32][33];
    const int tx = threadIdx.x, ty = threadIdx.y;       // (32, 8)
    const int j0 = blockIdx.x * 32, k0 = blockIdx.y * 32;
#pragma unroll
    for (int jj = 0; jj < 4; jj++) {
        const int k = k0 + ty + jj * 8;
        ts[ty + jj * 8][tx] = (k < HID) ? Wh[k * Z4 + j0 + tx]
                                        : Wattn[(k - HID) * Z4 + j0 + tx];
    }
    __syncthreads();
#pragma unroll
    for (int jj = 0; jj < 4; jj++) {
        const int jOut = j0 + ty + jj * 8;
        const int kOut = k0 + tx;
        g_wtb[(size_t)jOut * K2 + kOut] = __float2bfloat16(ts[tx][ty + jj * 8]);
    }
}

// ---------------- scores GEMM (tensor core): scores = hnb @ wvb^T + b ----------------
// M=128, N=128 per CTA, grid (79, 32), K=1024 in 32 chunks.
__global__ void __launch_bounds__(256) score_gemm_k(const float* __restrict__ b_vocab) {
    __shared__ __nv_bfloat16 sA[128 * SA];
    __shared__ __nv_bfloat16 sB[128 * SA];
    const int tid = threadIdx.x, lane = tid & 31, wid = tid >> 5;
    const int wm = (wid >> 2) * 64, wn = (wid & 3) * 32;
    const int r0 = blockIdx.y * 128, v0 = blockIdx.x * 128;
    const uint32_t sa = smem_u32(sA), sb = smem_u32(sB);

    float acc[4][4][4];
#pragma unroll
    for (int mi = 0; mi < 4; mi++)
#pragma unroll
        for (int ni = 0; ni < 4; ni++)
#pragma unroll
            for (int q = 0; q < 4; q++) acc[mi][ni][q] = 0.0f;

    const uint32_t aRow = lane & 15, aK = (lane >> 4) * 8;
    const uint32_t bRow = (lane & 7) + ((lane >> 4) << 3), bK = ((lane >> 3) & 1) * 8;

    for (int kc = 0; kc < HID; kc += 32) {
#pragma unroll
        for (int qq = 0; qq < 2; qq++) {
            const int q = tid + qq * 256;
            const int row = q >> 2, c4 = q & 3;
            *(uint4*)&sA[row * SA + c4 * 8] =
                *(const uint4*)&g_hnb[(r0 + row) * HID + kc + c4 * 8];
            *(uint4*)&sB[row * SA + c4 * 8] =
                *(const uint4*)&g_wvb[(v0 + row) * HID + kc + c4 * 8];
        }
        __syncthreads();
#pragma unroll
        for (int ks = 0; ks < 2; ks++) {
            uint32_t a[4][4], b[2][4];
#pragma unroll
            for (int mi = 0; mi < 4; mi++)
                ldsm4(a[mi], sa + ((wm + mi * 16 + aRow) * SA + ks * 16 + aK) * 2);
#pragma unroll
            for (int nh = 0; nh < 2; nh++)
                ldsm4(b[nh], sb + ((wn + nh * 16 + bRow) * SA + ks * 16 + bK) * 2);
#pragma unroll
            for (int mi = 0; mi < 4; mi++)
#pragma unroll
                for (int ni = 0; ni < 4; ni++)
                    mmabf16(acc[mi][ni], a[mi], &b[ni >> 1][(ni & 1) * 2]);
        }
        __syncthreads();
    }
    const int mBase = r0 + wm + (lane >> 2);
    const int nOff = 2 * (lane & 3);
#pragma unroll
    for (int mi = 0; mi < 4; mi++) {
#pragma unroll
        for (int ni = 0; ni < 4; ni++) {
            const int v = v0 + wn + ni * 8 + nOff;
            const float bv0 = (v < VOC) ? b_vocab[v] : 0.0f;
            const float bv1 = (v + 1 < VOC) ? b_vocab[v + 1] : 0.0f;
            const int m0 = mBase + mi * 16;
            float2 p0 = make_float2(acc[mi][ni][0] + bv0, acc[mi][ni][1] + bv1);
            float2 p1 = make_float2(acc[mi][ni][2] + bv0, acc[mi][ni][3] + bv1);
            *(float2*)&g_scores[(size_t)m0 * VOCP + v] = p0;
            *(float2*)&g_scores[(size_t)(m0 + 8) * VOCP + v] = p1;
        }
    }
}

// ---------------- streaming log-softmax NLL ----------------
__global__ void nll_k(const int* __restrict__ captions, float* __restrict__ out) {
    __shared__ float red[256];
    const int r = blockIdx.x, tid = threadIdx.x;
    const int t = r >> 7, n = r & 127;
    const float* row = g_scores + (size_t)r * VOCP;
    float s = 0.0f;
    for (int v = tid; v < VOC; v += 256) s += __expf(row[v]);
    red[tid] = s;
    __syncthreads();
    for (int st = 128; st > 0; st >>= 1) {
        if (tid < st) red[tid] += red[tid + st];
        __syncthreads();
    }
    if (tid == 0) {
        const int tg = captions[n * TCAP + t + 1];
        if (tg != 0) atomicAdd(out, (logf(red[0]) - row[tg]) * (1.0f / (float)NB));
    }
}

// ---------------- launcher ----------------
extern "C" void kernel_launch(void* const* d_in, const int* in_sizes, int n_in,
                              void* d_out, int out_size) {
    const float* features = (const float*)d_in[0];
    const int*   captions = (const int*)  d_in[1];
    const float* W_embed  = (const float*)d_in[2];
    const float* W_proj   = (const float*)d_in[3];
    const float* b_proj   = (const float*)d_in[4];
    const float* Wx       = (const float*)d_in[5];
    const float* Wh       = (const float*)d_in[6];
    const float* Wattn    = (const float*)d_in[7];
    const float* bvec     = (const float*)d_in[8];
    const float* W_vocab  = (const float*)d_in[9];
    const float* b_vocab  = (const float*)d_in[10];
    float* out = (float*)d_out;

    zero_out_k<<<1, 32>>>(out);
    compute_A_k<<<dim3(8, NB), 128>>>(features, W_proj, b_proj);
    embed_gemm_k<<<dim3(64, 64), 256>>>(captions, W_embed, Wx);
    conv_wt_k<<<dim3(Z4 / 32, K2 / 32), dim3(32, 8)>>>(Wh, Wattn);
    conv_wv_k<<<dim3(VOCP / 32, HID / 32), dim3(32, 8)>>>(W_vocab);
    for (int t = 0; t < TSTEPS; t++) {
        attn_k<<<NB, 512>>>();
        step_mma_k<<<64, 256>>>(bvec, t);
        gates_k<<<512, 256>>>(t);
    }
    score_gemm_k<<<dim3(VOCP / 128, NROWS / 128), 256>>>(b_vocab);
    nll_k<<<NROWS, 256>>>(captions, out);
}

// round 5
// speedup vs baseline: 5.6359x; 1.5886x over previous
#include <cuda_runtime.h>
#include <cuda_bf16.h>
#include <math.h>
#include <stdint.h>

// Problem constants
#define NB    128
#define TSTEPS 32
#define TCAP   33
#define DIM   400
#define HID  1024
#define EMB   512
#define K2   2048      // 2*HID
#define Z4   4096
#define VOC 10000
#define LPOS   16
#define NROWS (TSTEPS * NB)     // 4096
#define VOCP  10112             // 79 * 128
#define SA 40                   // padded smem stride (bf16): conflict-free ldmatrix

// ---------------- device scratch ----------------
__device__ float g_A[NB * LPOS * HID];
__device__ float g_hin[NB * 2 * HID];              // fp32 h0 (only init)
__device__ __nv_bfloat16 g_hinb[NB * K2];          // bf16 [h | attn]
__device__ float g_c[NB * HID];
__device__ float g_xWx[TSTEPS * NB * Z4];
__device__ float g_z[NB * Z4];
__device__ __nv_bfloat16 g_hnb[NROWS * HID];       // bf16 h history
__device__ __nv_bfloat16 g_wvb[VOCP * HID];        // bf16 W_vocab^T [v][k]
__device__ __nv_bfloat16 g_wtb[Z4 * K2];           // bf16 [Wh;Wattn]^T [j][k]
__device__ __nv_bfloat16 g_web[VOC * EMB];         // bf16 W_embed
__device__ __nv_bfloat16 g_wxt[Z4 * EMB];          // bf16 Wx^T [j][k]
__device__ float g_scores[(size_t)NROWS * VOCP];

// ---------------- helpers ----------------
__device__ __forceinline__ uint32_t smem_u32(const void* p) {
    uint32_t a;
    asm("{ .reg .u64 t; cvta.to.shared.u64 t, %1; cvt.u32.u64 %0, t; }" : "=r"(a) : "l"(p));
    return a;
}
__device__ __forceinline__ void ldsm4(uint32_t* r, uint32_t a) {
    asm volatile("ldmatrix.sync.aligned.m8n8.x4.shared.b16 {%0,%1,%2,%3}, [%4];"
        : "=r"(r[0]), "=r"(r[1]), "=r"(r[2]), "=r"(r[3]) : "r"(a));
}
__device__ __forceinline__ void mmabf16(float* d, const uint32_t* a, const uint32_t* b) {
    asm volatile("mma.sync.aligned.m16n8k16.row.col.f32.bf16.bf16.f32 "
        "{%0,%1,%2,%3}, {%4,%5,%6,%7}, {%8,%9}, {%0,%1,%2,%3};"
        : "+f"(d[0]), "+f"(d[1]), "+f"(d[2]), "+f"(d[3])
        : "r"(a[0]), "r"(a[1]), "r"(a[2]), "r"(a[3]), "r"(b[0]), "r"(b[1]));
}
__device__ __forceinline__ void cp16(uint32_t dst, const void* src) {
    asm volatile("cp.async.cg.shared.global [%0], [%1], 16;" :: "r"(dst), "l"(src));
}
#define CP_COMMIT() asm volatile("cp.async.commit_group;" ::: "memory")
#define CP_WAIT1()  asm volatile("cp.async.wait_group 1;" ::: "memory")
#define CP_WAIT0()  asm volatile("cp.async.wait_group 0;" ::: "memory")

// ---------------- zero out ----------------
__global__ void zero_out_k(float* o) { if (threadIdx.x == 0) o[0] = 0.0f; }

// ---------------- A projection + h0 ----------------
__global__ void compute_A_k(const float* __restrict__ features,
                            const float* __restrict__ W_proj,
                            const float* __restrict__ b_proj) {
    __shared__ float fsh[DIM * LPOS];
    const int n = blockIdx.y, tid = threadIdx.x;
    const float* fn = features + n * DIM * LPOS;
    for (int i = tid; i < DIM * LPOS; i += 128) fsh[i] = fn[i];
    __syncthreads();
    const int h = blockIdx.x * 128 + tid;
    float acc[LPOS];
#pragma unroll
    for (int l = 0; l < LPOS; l++) acc[l] = 0.0f;
    const float4* f4 = (const float4*)fsh;
    for (int d = 0; d < DIM; d++) {
        const float wp = W_proj[d * HID + h];
        const float4 a = f4[d * 4 + 0], b = f4[d * 4 + 1];
        const float4 c = f4[d * 4 + 2], e = f4[d * 4 + 3];
        float fv[LPOS] = {a.x, a.y, a.z, a.w, b.x, b.y, b.z, b.w,
                          c.x, c.y, c.z, c.w, e.x, e.y, e.z, e.w};
#pragma unroll
        for (int l = 0; l < LPOS; l++) acc[l] += fv[l] * wp;
    }
    const float bias = b_proj[h];
    float s = 0.0f;
#pragma unroll
    for (int l = 0; l < LPOS; l++) {
        const float v = acc[l] + bias;
        g_A[n * (LPOS * HID) + l * HID + h] = v;
        s += v;
    }
    const float h0 = s * (1.0f / 16.0f);
    g_hin[n * (2 * HID) + h] = h0;
    g_hinb[n * K2 + h] = __float2bfloat16(h0);
    g_c[n * HID + h] = h0;
}

// ---------------- conversions ----------------
__global__ void conv_we_k(const float* __restrict__ W_embed) {
    const int i = blockIdx.x * 1024 + threadIdx.x;
    if (i < VOC * EMB) g_web[i] = __float2bfloat16(W_embed[i]);
}
// Wx [EMB][Z4] -> g_wxt [Z4][EMB]
__global__ void conv_wxt_k(const float* __restrict__ Wx) {
    __shared__ float ts[32][33];
    const int tx = threadIdx.x, ty = threadIdx.y;       // (32, 8)
    const int j0 = blockIdx.x * 32, k0 = blockIdx.y * 32;
#pragma unroll
    for (int jj = 0; jj < 4; jj++) {
        const int k = k0 + ty + jj * 8;
        ts[ty + jj * 8][tx] = Wx[k * Z4 + j0 + tx];
    }
    __syncthreads();
#pragma unroll
    for (int jj = 0; jj < 4; jj++) {
        const int jOut = j0 + ty + jj * 8;
        const int kOut = k0 + tx;
        g_wxt[(size_t)jOut * EMB + kOut] = __float2bfloat16(ts[tx][ty + jj * 8]);
    }
}
// [Wh;Wattn] [K2][Z4] -> g_wtb [Z4][K2]
__global__ void conv_wt_k(const float* __restrict__ Wh,
                          const float* __restrict__ Wattn) {
    __shared__ float ts[32][33];
    const int tx = threadIdx.x, ty = threadIdx.y;
    const int j0 = blockIdx.x * 32, k0 = blockIdx.y * 32;
#pragma unroll
    for (int jj = 0; jj < 4; jj++) {
        const int k = k0 + ty + jj * 8;
        ts[ty + jj * 8][tx] = (k < HID) ? Wh[k * Z4 + j0 + tx]
                                        : Wattn[(k - HID) * Z4 + j0 + tx];
    }
    __syncthreads();
#pragma unroll
    for (int jj = 0; jj < 4; jj++) {
        const int jOut = j0 + ty + jj * 8;
        const int kOut = k0 + tx;
        g_wtb[(size_t)jOut * K2 + kOut] = __float2bfloat16(ts[tx][ty + jj * 8]);
    }
}
// W_vocab [HID][VOC] -> g_wvb [VOCP][HID], zero-padded
__global__ void conv_wv_k(const float* __restrict__ W_vocab) {
    __shared__ float ts[32][33];
    const int tx = threadIdx.x, ty = threadIdx.y;
    const int v0 = blockIdx.x * 32, k0 = blockIdx.y * 32;
    const int v = v0 + tx;
#pragma unroll
    for (int j = 0; j < 4; j++) {
        const int k = k0 + ty + j * 8;
        ts[ty + j * 8][tx] = (v < VOC) ? W_vocab[k * VOC + v] : 0.0f;
    }
    __syncthreads();
#pragma unroll
    for (int j = 0; j < 4; j++) {
        const int vOut = v0 + ty + j * 8;
        const int kOut = k0 + tx;
        g_wvb[vOut * HID + kOut] = __float2bfloat16(ts[tx][ty + j * 8]);
    }
}

// ---------------- embed GEMM (tensor core): xWx = W_embed[tok] @ Wx ----------------
// M=4096, N=4096, K=512. Tile 128x128, chunk 32, double-buffered cp.async.
__global__ void __launch_bounds__(256) embed_mma_k(const int* __restrict__ captions) {
    __shared__ __nv_bfloat16 sA[2][128 * SA];
    __shared__ __nv_bfloat16 sB[2][128 * SA];
    __shared__ int sTok[128];
    const int tid = threadIdx.x, lane = tid & 31, wid = tid >> 5;
    const int wm = (wid >> 2) * 64, wn = (wid & 3) * 32;
    const int r0 = blockIdx.y * 128, j0 = blockIdx.x * 128;
    const uint32_t saB[2] = {smem_u32(sA[0]), smem_u32(sA[1])};
    const uint32_t sbB[2] = {smem_u32(sB[0]), smem_u32(sB[1])};

    if (tid < 128) {
        const int r = r0 + tid, t = r >> 7, n = r & 127;
        sTok[tid] = captions[n * TCAP + t];
    }
    __syncthreads();

    float acc[4][4][4];
#pragma unroll
    for (int mi = 0; mi < 4; mi++)
#pragma unroll
        for (int ni = 0; ni < 4; ni++)
#pragma unroll
            for (int q = 0; q < 4; q++) acc[mi][ni][q] = 0.0f;

    const uint32_t aRow = lane & 15, aK = (lane >> 4) * 8;
    const uint32_t bRow = (lane & 7) + ((lane >> 4) << 3), bK = ((lane >> 3) & 1) * 8;

#define EMB_LOAD(buf, kc)                                                     \
    do {                                                                      \
        _Pragma("unroll")                                                     \
        for (int i = 0; i < 2; i++) {                                         \
            const int q = tid + i * 256;                                      \
            const int row = q >> 2, c4 = q & 3;                               \
            cp16(saB[buf] + row * (SA * 2) + c4 * 16,                         \
                 &g_web[(size_t)sTok[row] * EMB + (kc) + c4 * 8]);            \
            cp16(sbB[buf] + row * (SA * 2) + c4 * 16,                         \
                 &g_wxt[(size_t)(j0 + row) * EMB + (kc) + c4 * 8]);           \
        }                                                                     \
    } while (0)

    EMB_LOAD(0, 0); CP_COMMIT();
    for (int ch = 0; ch < 16; ch++) {
        if (ch + 1 < 16) { EMB_LOAD((ch + 1) & 1, (ch + 1) * 32); CP_COMMIT(); CP_WAIT1(); }
        else CP_WAIT0();
        __syncthreads();
        const uint32_t sa = saB[ch & 1], sb = sbB[ch & 1];
#pragma unroll
        for (int ks = 0; ks < 2; ks++) {
            uint32_t a[4][4], b[2][4];
#pragma unroll
            for (int mi = 0; mi < 4; mi++)
                ldsm4(a[mi], sa + ((wm + mi * 16 + aRow) * SA + ks * 16 + aK) * 2);
#pragma unroll
            for (int nh = 0; nh < 2; nh++)
                ldsm4(b[nh], sb + ((wn + nh * 16 + bRow) * SA + ks * 16 + bK) * 2);
#pragma unroll
            for (int mi = 0; mi < 4; mi++)
#pragma unroll
                for (int ni = 0; ni < 4; ni++)
                    mmabf16(acc[mi][ni], a[mi], &b[ni >> 1][(ni & 1) * 2]);
        }
        __syncthreads();
    }
    const int mBase = r0 + wm + (lane >> 2);
    const int nOff = 2 * (lane & 3);
#pragma unroll
    for (int mi = 0; mi < 4; mi++) {
#pragma unroll
        for (int ni = 0; ni < 4; ni++) {
            const int j = j0 + wn + ni * 8 + nOff;
            const int m0 = mBase + mi * 16;
            *(float2*)&g_xWx[(size_t)m0 * Z4 + j] = make_float2(acc[mi][ni][0], acc[mi][ni][1]);
            *(float2*)&g_xWx[(size_t)(m0 + 8) * Z4 + j] = make_float2(acc[mi][ni][2], acc[mi][ni][3]);
        }
    }
}

// ---------------- fused gates(t-1) + attention(t) ----------------
// t in [0, 32]. Phase1 (gates for step t-1) if t>0; Phase2 (attn for step t) if t<32.
__global__ void __launch_bounds__(512) fused_ga_k(int t) {
    __shared__ float hsh[HID];
    __shared__ float e_sh[LPOS];
    __shared__ float w_sh[LPOS];
    const int n = blockIdx.x, tid = threadIdx.x;
    const int warp = tid >> 5, lane = tid & 31;

    if (t > 0) {
        const float* zr = g_z + n * Z4;
        for (int h = tid; h < HID; h += 512) {
            const float ai = zr[h], af = zr[h + HID], ao = zr[h + 2 * HID], ag = zr[h + 3 * HID];
            const float gi = 1.0f / (1.0f + expf(-ai));
            const float gf = 1.0f / (1.0f + expf(-af));
            const float go = 1.0f / (1.0f + expf(-ao));
            const float gg = tanhf(ag);
            const float c = gf * g_c[n * HID + h] + gi * gg;
            const float hh = go * tanhf(c);
            g_c[n * HID + h] = c;
            hsh[h] = hh;
            g_hinb[n * K2 + h] = __float2bfloat16(hh);
            g_hnb[(size_t)(t - 1) * (NB * HID) + n * HID + h] = __float2bfloat16(hh);
        }
    } else {
        for (int h = tid; h < HID; h += 512) hsh[h] = g_hin[n * (2 * HID) + h];
    }
    __syncthreads();

    if (t < TSTEPS) {
        const float* An = g_A + n * (LPOS * HID);
        float s = 0.0f;
        const float* Al = An + warp * HID;
        for (int h = lane; h < HID; h += 32) s += hsh[h] * Al[h];
#pragma unroll
        for (int off = 16; off > 0; off >>= 1) s += __shfl_down_sync(0xFFFFFFFF, s, off);
        if (lane == 0) e_sh[warp] = s * 0.03125f;
        __syncthreads();
        if (tid == 0) {
            float m = -1e30f;
#pragma unroll
            for (int l = 0; l < LPOS; l++) m = fmaxf(m, e_sh[l]);
            float ss = 0.0f;
#pragma unroll
            for (int l = 0; l < LPOS; l++) { float w = expf(e_sh[l] - m); w_sh[l] = w; ss += w; }
            const float inv = 1.0f / ss;
#pragma unroll
            for (int l = 0; l < LPOS; l++) w_sh[l] *= inv;
        }
        __syncthreads();
        for (int h = tid; h < HID; h += 512) {
            float a = 0.0f;
#pragma unroll
            for (int l = 0; l < LPOS; l++) a += An[l * HID + h] * w_sh[l];
            g_hinb[n * K2 + HID + h] = __float2bfloat16(a);
        }
    }
}

// ---------------- step GEMM (tensor core): z = hinb @ wtb^T + xWx + b ----------------
// M=128, N=64/CTA (grid 64), K=2048 chunk 32, double-buffered.
__global__ void __launch_bounds__(256) step_mma_k(const float* __restrict__ bvec, int t) {
    __shared__ __nv_bfloat16 sA[2][128 * SA];
    __shared__ __nv_bfloat16 sB[2][64 * SA];
    const int tid = threadIdx.x, lane = tid & 31, wid = tid >> 5;
    const int wm = (wid >> 2) * 64, wn = (wid & 3) * 16;
    const int j0 = blockIdx.x * 64;
    const uint32_t saB[2] = {smem_u32(sA[0]), smem_u32(sA[1])};
    const uint32_t sbB[2] = {smem_u32(sB[0]), smem_u32(sB[1])};

    float acc[4][2][4];
#pragma unroll
    for (int mi = 0; mi < 4; mi++)
#pragma unroll
        for (int ni = 0; ni < 2; ni++)
#pragma unroll
            for (int q = 0; q < 4; q++) acc[mi][ni][q] = 0.0f;

    const uint32_t aRow = lane & 15, aK = (lane >> 4) * 8;
    const uint32_t bRow = (lane & 7) + ((lane >> 4) << 3), bK = ((lane >> 3) & 1) * 8;

#define STEP_LOAD(buf, kc)                                                    \
    do {                                                                      \
        _Pragma("unroll")                                                     \
        for (int i = 0; i < 2; i++) {                                         \
            const int q = tid + i * 256;                                      \
            const int row = q >> 2, c4 = q & 3;                               \
            cp16(saB[buf] + row * (SA * 2) + c4 * 16,                         \
                 &g_hinb[row * K2 + (kc) + c4 * 8]);                          \
        }                                                                     \
        {                                                                     \
            const int row = tid >> 2, c4 = tid & 3;                           \
            cp16(sbB[buf] + row * (SA * 2) + c4 * 16,                         \
                 &g_wtb[(size_t)(j0 + row) * K2 + (kc) + c4 * 8]);            \
        }                                                                     \
    } while (0)

    STEP_LOAD(0, 0); CP_COMMIT();
    for (int ch = 0; ch < 64; ch++) {
        if (ch + 1 < 64) { STEP_LOAD((ch + 1) & 1, (ch + 1) * 32); CP_COMMIT(); CP_WAIT1(); }
        else CP_WAIT0();
        __syncthreads();
        const uint32_t sa = saB[ch & 1], sb = sbB[ch & 1];
#pragma unroll
        for (int ks = 0; ks < 2; ks++) {
            uint32_t a[4][4], b[4];
#pragma unroll
            for (int mi = 0; mi < 4; mi++)
                ldsm4(a[mi], sa + ((wm + mi * 16 + aRow) * SA + ks * 16 + aK) * 2);
            ldsm4(b, sb + ((wn + bRow) * SA + ks * 16 + bK) * 2);
#pragma unroll
            for (int mi = 0; mi < 4; mi++)
#pragma unroll
                for (int ni = 0; ni < 2; ni++)
                    mmabf16(acc[mi][ni], a[mi], &b[ni * 2]);
        }
        __syncthreads();
    }
    const int mBase = wm + (lane >> 2);
    const int nOff = 2 * (lane & 3);
#pragma unroll
    for (int mi = 0; mi < 4; mi++) {
#pragma unroll
        for (int ni = 0; ni < 2; ni++) {
            const int j = j0 + wn + ni * 8 + nOff;
            const float2 bb = *(const float2*)&bvec[j];
            const int m0 = mBase + mi * 16;
            const float2 x0 = *(const float2*)&g_xWx[(size_t)(t * NB + m0) * Z4 + j];
            const float2 x1 = *(const float2*)&g_xWx[(size_t)(t * NB + m0 + 8) * Z4 + j];
            *(float2*)&g_z[m0 * Z4 + j] =
                make_float2(acc[mi][ni][0] + x0.x + bb.x, acc[mi][ni][1] + x0.y + bb.y);
            *(float2*)&g_z[(m0 + 8) * Z4 + j] =
                make_float2(acc[mi][ni][2] + x1.x + bb.x, acc[mi][ni][3] + x1.y + bb.y);
        }
    }
}

// ---------------- scores GEMM (tensor core): scores = hnb @ wvb^T + b ----------------
// M=128, N=128/CTA, grid (79, 32), K=1024 chunk 32, double-buffered.
__global__ void __launch_bounds__(256) score_gemm_k(const float* __restrict__ b_vocab) {
    __shared__ __nv_bfloat16 sA[2][128 * SA];
    __shared__ __nv_bfloat16 sB[2][128 * SA];
    const int tid = threadIdx.x, lane = tid & 31, wid = tid >> 5;
    const int wm = (wid >> 2) * 64, wn = (wid & 3) * 32;
    const int r0 = blockIdx.y * 128, v0 = blockIdx.x * 128;
    const uint32_t saB[2] = {smem_u32(sA[0]), smem_u32(sA[1])};
    const uint32_t sbB[2] = {smem_u32(sB[0]), smem_u32(sB[1])};

    float acc[4][4][4];
#pragma unroll
    for (int mi = 0; mi < 4; mi++)
#pragma unroll
        for (int ni = 0; ni < 4; ni++)
#pragma unroll
            for (int q = 0; q < 4; q++) acc[mi][ni][q] = 0.0f;

    const uint32_t aRow = lane & 15, aK = (lane >> 4) * 8;
    const uint32_t bRow = (lane & 7) + ((lane >> 4) << 3), bK = ((lane >> 3) & 1) * 8;

#define SC_LOAD(buf, kc)                                                      \
    do {                                                                      \
        _Pragma("unroll")                                                     \
        for (int i = 0; i < 2; i++) {                                         \
            const int q = tid + i * 256;                                      \
            const int row = q >> 2, c4 = q & 3;                               \
            cp16(saB[buf] + row * (SA * 2) + c4 * 16,                         \
                 &g_hnb[(size_t)(r0 + row) * HID + (kc) + c4 * 8]);           \
            cp16(sbB[buf] + row * (SA * 2) + c4 * 16,                         \
                 &g_wvb[(size_t)(v0 + row) * HID + (kc) + c4 * 8]);           \
        }                                                                     \
    } while (0)

    SC_LOAD(0, 0); CP_COMMIT();
    for (int ch = 0; ch < 32; ch++) {
        if (ch + 1 < 32) { SC_LOAD((ch + 1) & 1, (ch + 1) * 32); CP_COMMIT(); CP_WAIT1(); }
        else CP_WAIT0();
        __syncthreads();
        const uint32_t sa = saB[ch & 1], sb = sbB[ch & 1];
#pragma unroll
        for (int ks = 0; ks < 2; ks++) {
            uint32_t a[4][4], b[2][4];
#pragma unroll
            for (int mi = 0; mi < 4; mi++)
                ldsm4(a[mi], sa + ((wm + mi * 16 + aRow) * SA + ks * 16 + aK) * 2);
#pragma unroll
            for (int nh = 0; nh < 2; nh++)
                ldsm4(b[nh], sb + ((wn + nh * 16 + bRow) * SA + ks * 16 + bK) * 2);
#pragma unroll
            for (int mi = 0; mi < 4; mi++)
#pragma unroll
                for (int ni = 0; ni < 4; ni++)
                    mmabf16(acc[mi][ni], a[mi], &b[ni >> 1][(ni & 1) * 2]);
        }
        __syncthreads();
    }
    const int mBase = r0 + wm + (lane >> 2);
    const int nOff = 2 * (lane & 3);
#pragma unroll
    for (int mi = 0; mi < 4; mi++) {
#pragma unroll
        for (int ni = 0; ni < 4; ni++) {
            const int v = v0 + wn + ni * 8 + nOff;
            const float bv0 = (v < VOC) ? b_vocab[v] : 0.0f;
            const float bv1 = (v + 1 < VOC) ? b_vocab[v + 1] : 0.0f;
            const int m0 = mBase + mi * 16;
            *(float2*)&g_scores[(size_t)m0 * VOCP + v] =
                make_float2(acc[mi][ni][0] + bv0, acc[mi][ni][1] + bv1);
            *(float2*)&g_scores[(size_t)(m0 + 8) * VOCP + v] =
                make_float2(acc[mi][ni][2] + bv0, acc[mi][ni][3] + bv1);
        }
    }
}

// ---------------- streaming log-softmax NLL ----------------
__global__ void nll_k(const int* __restrict__ captions, float* __restrict__ out) {
    __shared__ float red[256];
    const int r = blockIdx.x, tid = threadIdx.x;
    const int t = r >> 7, n = r & 127;
    const float* row = g_scores + (size_t)r * VOCP;
    float s = 0.0f;
    for (int v = tid; v < VOC; v += 256) s += __expf(row[v]);
    red[tid] = s;
    __syncthreads();
    for (int st = 128; st > 0; st >>= 1) {
        if (tid < st) red[tid] += red[tid + st];
        __syncthreads();
    }
    if (tid == 0) {
        const int tg = captions[n * TCAP + t + 1];
        if (tg != 0) atomicAdd(out, (logf(red[0]) - row[tg]) * (1.0f / (float)NB));
    }
}

// ---------------- launcher ----------------
extern "C" void kernel_launch(void* const* d_in, const int* in_sizes, int n_in,
                              void* d_out, int out_size) {
    const float* features = (const float*)d_in[0];
    const int*   captions = (const int*)  d_in[1];
    const float* W_embed  = (const float*)d_in[2];
    const float* W_proj   = (const float*)d_in[3];
    const float* b_proj   = (const float*)d_in[4];
    const float* Wx       = (const float*)d_in[5];
    const float* Wh       = (const float*)d_in[6];
    const float* Wattn    = (const float*)d_in[7];
    const float* bvec     = (const float*)d_in[8];
    const float* W_vocab  = (const float*)d_in[9];
    const float* b_vocab  = (const float*)d_in[10];
    float* out = (float*)d_out;

    zero_out_k<<<1, 32>>>(out);
    compute_A_k<<<dim3(8, NB), 128>>>(features, W_proj, b_proj);
    conv_we_k<<<(VOC * EMB + 1023) / 1024, 1024>>>(W_embed);
    conv_wxt_k<<<dim3(Z4 / 32, EMB / 32), dim3(32, 8)>>>(Wx);
    conv_wt_k<<<dim3(Z4 / 32, K2 / 32), dim3(32, 8)>>>(Wh, Wattn);
    conv_wv_k<<<dim3(VOCP / 32, HID / 32), dim3(32, 8)>>>(W_vocab);
    embed_mma_k<<<dim3(Z4 / 128, NROWS / 128), 256>>>(captions);
    for (int t = 0; t < TSTEPS; t++) {
        fused_ga_k<<<NB, 512>>>(t);
        step_mma_k<<<64, 256>>>(bvec, t);
    }
    fused_ga_k<<<NB, 512>>>(TSTEPS);   // final gates for t=31
    score_gemm_k<<<dim3(VOCP / 128, NROWS / 128), 256>>>(b_vocab);
    nll_k<<<NROWS, 256>>>(captions, out);
}

// round 6
// speedup vs baseline: 5.6416x; 1.0010x over previous
#include <cuda_runtime.h>
#include <cuda_bf16.h>
#include <math.h>
#include <stdint.h>

// Problem constants
#define NB    128
#define TSTEPS 32
#define TCAP   33
#define DIM   400
#define HID  1024
#define EMB   512
#define K2   2048      // 2*HID
#define Z4   4096
#define VOC 10000
#define LPOS   16
#define NROWS (TSTEPS * NB)     // 4096
#define VOCP  10112             // 79 * 128
#define SA 40                   // padded smem stride (bf16): conflict-free ldmatrix

// ---------------- device scratch ----------------
__device__ float g_A[NB * LPOS * HID];
__device__ float g_hin[NB * 2 * HID];              // fp32 h0 (only init)
__device__ __nv_bfloat16 g_hinb[NB * K2];          // bf16 [h | attn]
__device__ float g_c[NB * HID];
__device__ float g_xWx[TSTEPS * NB * Z4];
__device__ float g_z[NB * Z4];
__device__ __nv_bfloat16 g_hnb[NROWS * HID];       // bf16 h history
__device__ __nv_bfloat16 g_wvb[VOCP * HID];        // bf16 W_vocab^T [v][k]
__device__ __nv_bfloat16 g_wtb[Z4 * K2];           // bf16 [Wh;Wattn]^T [j][k]
__device__ __nv_bfloat16 g_web[VOC * EMB];         // bf16 W_embed
__device__ __nv_bfloat16 g_wxt[Z4 * EMB];          // bf16 Wx^T [j][k]
__device__ float g_scores[(size_t)NROWS * VOCP];

// ---------------- helpers ----------------
__device__ __forceinline__ uint32_t smem_u32(const void* p) {
    uint32_t a;
    asm("{ .reg .u64 t; cvta.to.shared.u64 t, %1; cvt.u32.u64 %0, t; }" : "=r"(a) : "l"(p));
    return a;
}
__device__ __forceinline__ void ldsm4(uint32_t* r, uint32_t a) {
    asm volatile("ldmatrix.sync.aligned.m8n8.x4.shared.b16 {%0,%1,%2,%3}, [%4];"
        : "=r"(r[0]), "=r"(r[1]), "=r"(r[2]), "=r"(r[3]) : "r"(a));
}
__device__ __forceinline__ void mmabf16(float* d, const uint32_t* a, const uint32_t* b) {
    asm volatile("mma.sync.aligned.m16n8k16.row.col.f32.bf16.bf16.f32 "
        "{%0,%1,%2,%3}, {%4,%5,%6,%7}, {%8,%9}, {%0,%1,%2,%3};"
        : "+f"(d[0]), "+f"(d[1]), "+f"(d[2]), "+f"(d[3])
        : "r"(a[0]), "r"(a[1]), "r"(a[2]), "r"(a[3]), "r"(b[0]), "r"(b[1]));
}
__device__ __forceinline__ void cp16(uint32_t dst, const void* src) {
    asm volatile("cp.async.cg.shared.global [%0], [%1], 16;" :: "r"(dst), "l"(src));
}
#define CP_COMMIT() asm volatile("cp.async.commit_group;" ::: "memory")
#define CP_WAIT1()  asm volatile("cp.async.wait_group 1;" ::: "memory")
#define CP_WAIT0()  asm volatile("cp.async.wait_group 0;" ::: "memory")

// ---------------- zero out ----------------
__global__ void zero_out_k(float* o) { if (threadIdx.x == 0) o[0] = 0.0f; }

// ---------------- A projection + h0 ----------------
__global__ void compute_A_k(const float* __restrict__ features,
                            const float* __restrict__ W_proj,
                            const float* __restrict__ b_proj) {
    __shared__ float fsh[DIM * LPOS];
    const int n = blockIdx.y, tid = threadIdx.x;
    const float* fn = features + n * DIM * LPOS;
    for (int i = tid; i < DIM * LPOS; i += 128) fsh[i] = fn[i];
    __syncthreads();
    const int h = blockIdx.x * 128 + tid;
    float acc[LPOS];
#pragma unroll
    for (int l = 0; l < LPOS; l++) acc[l] = 0.0f;
    const float4* f4 = (const float4*)fsh;
    for (int d = 0; d < DIM; d++) {
        const float wp = W_proj[d * HID + h];
        const float4 a = f4[d * 4 + 0], b = f4[d * 4 + 1];
        const float4 c = f4[d * 4 + 2], e = f4[d * 4 + 3];
        float fv[LPOS] = {a.x, a.y, a.z, a.w, b.x, b.y, b.z, b.w,
                          c.x, c.y, c.z, c.w, e.x, e.y, e.z, e.w};
#pragma unroll
        for (int l = 0; l < LPOS; l++) acc[l] += fv[l] * wp;
    }
    const float bias = b_proj[h];
    float s = 0.0f;
#pragma unroll
    for (int l = 0; l < LPOS; l++) {
        const float v = acc[l] + bias;
        g_A[n * (LPOS * HID) + l * HID + h] = v;
        s += v;
    }
    const float h0 = s * (1.0f / 16.0f);
    g_hin[n * (2 * HID) + h] = h0;
    g_hinb[n * K2 + h] = __float2bfloat16(h0);
    g_c[n * HID + h] = h0;
}

// ---------------- conversions ----------------
__global__ void conv_we_k(const float* __restrict__ W_embed) {
    const int i = blockIdx.x * 1024 + threadIdx.x;
    if (i < VOC * EMB) g_web[i] = __float2bfloat16(W_embed[i]);
}
// Wx [EMB][Z4] -> g_wxt [Z4][EMB]
__global__ void conv_wxt_k(const float* __restrict__ Wx) {
    __shared__ float ts[32][33];
    const int tx = threadIdx.x, ty = threadIdx.y;       // (32, 8)
    const int j0 = blockIdx.x * 32, k0 = blockIdx.y * 32;
#pragma unroll
    for (int jj = 0; jj < 4; jj++) {
        const int k = k0 + ty + jj * 8;
        ts[ty + jj * 8][tx] = Wx[k * Z4 + j0 + tx];
    }
    __syncthreads();
#pragma unroll
    for (int jj = 0; jj < 4; jj++) {
        const int jOut = j0 + ty + jj * 8;
        const int kOut = k0 + tx;
        g_wxt[(size_t)jOut * EMB + kOut] = __float2bfloat16(ts[tx][ty + jj * 8]);
    }
}
// [Wh;Wattn] [K2][Z4] -> g_wtb [Z4][K2]
__global__ void conv_wt_k(const float* __restrict__ Wh,
                          const float* __restrict__ Wattn) {
    __shared__ float ts[32][33];
    const int tx = threadIdx.x, ty = threadIdx.y;
    const int j0 = blockIdx.x * 32, k0 = blockIdx.y * 32;
#pragma unroll
    for (int jj = 0; jj < 4; jj++) {
        const int k = k0 + ty + jj * 8;
        ts[ty + jj * 8][tx] = (k < HID) ? Wh[k * Z4 + j0 + tx]
                                        : Wattn[(k - HID) * Z4 + j0 + tx];
    }
    __syncthreads();
#pragma unroll
    for (int jj = 0; jj < 4; jj++) {
        const int jOut = j0 + ty + jj * 8;
        const int kOut = k0 + tx;
        g_wtb[(size_t)jOut * K2 + kOut] = __float2bfloat16(ts[tx][ty + jj * 8]);
    }
}
// W_vocab [HID][VOC] -> g_wvb [VOCP][HID], zero-padded
__global__ void conv_wv_k(const float* __restrict__ W_vocab) {
    __shared__ float ts[32][33];
    const int tx = threadIdx.x, ty = threadIdx.y;
    const int v0 = blockIdx.x * 32, k0 = blockIdx.y * 32;
    const int v = v0 + tx;
#pragma unroll
    for (int j = 0; j < 4; j++) {
        const int k = k0 + ty + j * 8;
        ts[ty + j * 8][tx] = (v < VOC) ? W_vocab[k * VOC + v] : 0.0f;
    }
    __syncthreads();
#pragma unroll
    for (int j = 0; j < 4; j++) {
        const int vOut = v0 + ty + j * 8;
        const int kOut = k0 + tx;
        g_wvb[vOut * HID + kOut] = __float2bfloat16(ts[tx][ty + j * 8]);
    }
}

// ---------------- embed GEMM (tensor core): xWx = W_embed[tok] @ Wx ----------------
// M=4096, N=4096, K=512. Tile 128x128, chunk 32, double-buffered cp.async.
__global__ void __launch_bounds__(256) embed_mma_k(const int* __restrict__ captions) {
    __shared__ __nv_bfloat16 sA[2][128 * SA];
    __shared__ __nv_bfloat16 sB[2][128 * SA];
    __shared__ int sTok[128];
    const int tid = threadIdx.x, lane = tid & 31, wid = tid >> 5;
    const int wm = (wid >> 2) * 64, wn = (wid & 3) * 32;
    const int r0 = blockIdx.y * 128, j0 = blockIdx.x * 128;
    const uint32_t saB[2] = {smem_u32(sA[0]), smem_u32(sA[1])};
    const uint32_t sbB[2] = {smem_u32(sB[0]), smem_u32(sB[1])};

    if (tid < 128) {
        const int r = r0 + tid, t = r >> 7, n = r & 127;
        sTok[tid] = captions[n * TCAP + t];
    }
    __syncthreads();

    float acc[4][4][4];
#pragma unroll
    for (int mi = 0; mi < 4; mi++)
#pragma unroll
        for (int ni = 0; ni < 4; ni++)
#pragma unroll
            for (int q = 0; q < 4; q++) acc[mi][ni][q] = 0.0f;

    const uint32_t aRow = lane & 15, aK = (lane >> 4) * 8;
    const uint32_t bRow = (lane & 7) + ((lane >> 4) << 3), bK = ((lane >> 3) & 1) * 8;

#define EMB_LOAD(buf, kc)                                                     \
    do {                                                                      \
        _Pragma("unroll")                                                     \
        for (int i = 0; i < 2; i++) {                                         \
            const int q = tid + i * 256;                                      \
            const int row = q >> 2, c4 = q & 3;                               \
            cp16(saB[buf] + row * (SA * 2) + c4 * 16,                         \
                 &g_web[(size_t)sTok[row] * EMB + (kc) + c4 * 8]);            \
            cp16(sbB[buf] + row * (SA * 2) + c4 * 16,                         \
                 &g_wxt[(size_t)(j0 + row) * EMB + (kc) + c4 * 8]);           \
        }                                                                     \
    } while (0)

    EMB_LOAD(0, 0); CP_COMMIT();
    for (int ch = 0; ch < 16; ch++) {
        if (ch + 1 < 16) { EMB_LOAD((ch + 1) & 1, (ch + 1) * 32); CP_COMMIT(); CP_WAIT1(); }
        else CP_WAIT0();
        __syncthreads();
        const uint32_t sa = saB[ch & 1], sb = sbB[ch & 1];
#pragma unroll
        for (int ks = 0; ks < 2; ks++) {
            uint32_t a[4][4], b[2][4];
#pragma unroll
            for (int mi = 0; mi < 4; mi++)
                ldsm4(a[mi], sa + ((wm + mi * 16 + aRow) * SA + ks * 16 + aK) * 2);
#pragma unroll
            for (int nh = 0; nh < 2; nh++)
                ldsm4(b[nh], sb + ((wn + nh * 16 + bRow) * SA + ks * 16 + bK) * 2);
#pragma unroll
            for (int mi = 0; mi < 4; mi++)
#pragma unroll
                for (int ni = 0; ni < 4; ni++)
                    mmabf16(acc[mi][ni], a[mi], &b[ni >> 1][(ni & 1) * 2]);
        }
        __syncthreads();
    }
    const int mBase = r0 + wm + (lane >> 2);
    const int nOff = 2 * (lane & 3);
#pragma unroll
    for (int mi = 0; mi < 4; mi++) {
#pragma unroll
        for (int ni = 0; ni < 4; ni++) {
            const int j = j0 + wn + ni * 8 + nOff;
            const int m0 = mBase + mi * 16;
            *(float2*)&g_xWx[(size_t)m0 * Z4 + j] = make_float2(acc[mi][ni][0], acc[mi][ni][1]);
            *(float2*)&g_xWx[(size_t)(m0 + 8) * Z4 + j] = make_float2(acc[mi][ni][2], acc[mi][ni][3]);
        }
    }
}

// ---------------- fused gates(t-1) + attention(t) ----------------
// t in [0, 32]. Phase1 (gates for step t-1) if t>0; Phase2 (attn for step t) if t<32.
__global__ void __launch_bounds__(512) fused_ga_k(int t) {
    __shared__ float hsh[HID];
    __shared__ float e_sh[LPOS];
    __shared__ float w_sh[LPOS];
    const int n = blockIdx.x, tid = threadIdx.x;
    const int warp = tid >> 5, lane = tid & 31;

    if (t > 0) {
        const float* zr = g_z + n * Z4;
        for (int h = tid; h < HID; h += 512) {
            const float ai = zr[h], af = zr[h + HID], ao = zr[h + 2 * HID], ag = zr[h + 3 * HID];
            const float gi = 1.0f / (1.0f + expf(-ai));
            const float gf = 1.0f / (1.0f + expf(-af));
            const float go = 1.0f / (1.0f + expf(-ao));
            const float gg = tanhf(ag);
            const float c = gf * g_c[n * HID + h] + gi * gg;
            const float hh = go * tanhf(c);
            g_c[n * HID + h] = c;
            hsh[h] = hh;
            g_hinb[n * K2 + h] = __float2bfloat16(hh);
            g_hnb[(size_t)(t - 1) * (NB * HID) + n * HID + h] = __float2bfloat16(hh);
        }
    } else {
        for (int h = tid; h < HID; h += 512) hsh[h] = g_hin[n * (2 * HID) + h];
    }
    __syncthreads();

    if (t < TSTEPS) {
        const float* An = g_A + n * (LPOS * HID);
        float s = 0.0f;
        const float* Al = An + warp * HID;
        for (int h = lane; h < HID; h += 32) s += hsh[h] * Al[h];
#pragma unroll
        for (int off = 16; off > 0; off >>= 1) s += __shfl_down_sync(0xFFFFFFFF, s, off);
        if (lane == 0) e_sh[warp] = s * 0.03125f;
        __syncthreads();
        if (tid == 0) {
            float m = -1e30f;
#pragma unroll
            for (int l = 0; l < LPOS; l++) m = fmaxf(m, e_sh[l]);
            float ss = 0.0f;
#pragma unroll
            for (int l = 0; l < LPOS; l++) { float w = expf(e_sh[l] - m); w_sh[l] = w; ss += w; }
            const float inv = 1.0f / ss;
#pragma unroll
            for (int l = 0; l < LPOS; l++) w_sh[l] *= inv;
        }
        __syncthreads();
        for (int h = tid; h < HID; h += 512) {
            float a = 0.0f;
#pragma unroll
            for (int l = 0; l < LPOS; l++) a += An[l * HID + h] * w_sh[l];
            g_hinb[n * K2 + HID + h] = __float2bfloat16(a);
        }
    }
}

// ---------------- step GEMM (tensor core): z = hinb @ wtb^T + xWx + b ----------------
// M=128, N=64/CTA (grid 64), K=2048 chunk 32, double-buffered.
__global__ void __launch_bounds__(256) step_mma_k(const float* __restrict__ bvec, int t) {
    __shared__ __nv_bfloat16 sA[2][128 * SA];
    __shared__ __nv_bfloat16 sB[2][64 * SA];
    const int tid = threadIdx.x, lane = tid & 31, wid = tid >> 5;
    const int wm = (wid >> 2) * 64, wn = (wid & 3) * 16;
    const int j0 = blockIdx.x * 64;
    const uint32_t saB[2] = {smem_u32(sA[0]), smem_u32(sA[1])};
    const uint32_t sbB[2] = {smem_u32(sB[0]), smem_u32(sB[1])};

    float acc[4][2][4];
#pragma unroll
    for (int mi = 0; mi < 4; mi++)
#pragma unroll
        for (int ni = 0; ni < 2; ni++)
#pragma unroll
            for (int q = 0; q < 4; q++) acc[mi][ni][q] = 0.0f;

    const uint32_t aRow = lane & 15, aK = (lane >> 4) * 8;
    const uint32_t bRow = (lane & 7) + ((lane >> 4) << 3), bK = ((lane >> 3) & 1) * 8;

#define STEP_LOAD(buf, kc)                                                    \
    do {                                                                      \
        _Pragma("unroll")                                                     \
        for (int i = 0; i < 2; i++) {                                         \
            const int q = tid + i * 256;                                      \
            const int row = q >> 2, c4 = q & 3;                               \
            cp16(saB[buf] + row * (SA * 2) + c4 * 16,                         \
                 &g_hinb[row * K2 + (kc) + c4 * 8]);                          \
        }                                                                     \
        {                                                                     \
            const int row = tid >> 2, c4 = tid & 3;                           \
            cp16(sbB[buf] + row * (SA * 2) + c4 * 16,                         \
                 &g_wtb[(size_t)(j0 + row) * K2 + (kc) + c4 * 8]);            \
        }                                                                     \
    } while (0)

    STEP_LOAD(0, 0); CP_COMMIT();
    for (int ch = 0; ch < 64; ch++) {
        if (ch + 1 < 64) { STEP_LOAD((ch + 1) & 1, (ch + 1) * 32); CP_COMMIT(); CP_WAIT1(); }
        else CP_WAIT0();
        __syncthreads();
        const uint32_t sa = saB[ch & 1], sb = sbB[ch & 1];
#pragma unroll
        for (int ks = 0; ks < 2; ks++) {
            uint32_t a[4][4], b[4];
#pragma unroll
            for (int mi = 0; mi < 4; mi++)
                ldsm4(a[mi], sa + ((wm + mi * 16 + aRow) * SA + ks * 16 + aK) * 2);
            ldsm4(b, sb + ((wn + bRow) * SA + ks * 16 + bK) * 2);
#pragma unroll
            for (int mi = 0; mi < 4; mi++)
#pragma unroll
                for (int ni = 0; ni < 2; ni++)
                    mmabf16(acc[mi][ni], a[mi], &b[ni * 2]);
        }
        __syncthreads();
    }
    const int mBase = wm + (lane >> 2);
    const int nOff = 2 * (lane & 3);
#pragma unroll
    for (int mi = 0; mi < 4; mi++) {
#pragma unroll
        for (int ni = 0; ni < 2; ni++) {
            const int j = j0 + wn + ni * 8 + nOff;
            const float2 bb = *(const float2*)&bvec[j];
            const int m0 = mBase + mi * 16;
            const float2 x0 = *(const float2*)&g_xWx[(size_t)(t * NB + m0) * Z4 + j];
            const float2 x1 = *(const float2*)&g_xWx[(size_t)(t * NB + m0 + 8) * Z4 + j];
            *(float2*)&g_z[m0 * Z4 + j] =
                make_float2(acc[mi][ni][0] + x0.x + bb.x, acc[mi][ni][1] + x0.y + bb.y);
            *(float2*)&g_z[(m0 + 8) * Z4 + j] =
                make_float2(acc[mi][ni][2] + x1.x + bb.x, acc[mi][ni][3] + x1.y + bb.y);
        }
    }
}

// ---------------- scores GEMM (tensor core): scores = hnb @ wvb^T + b ----------------
// M=128, N=128/CTA, grid (79, 32), K=1024 chunk 32, double-buffered.
__global__ void __launch_bounds__(256) score_gemm_k(const float* __restrict__ b_vocab) {
    __shared__ __nv_bfloat16 sA[2][128 * SA];
    __shared__ __nv_bfloat16 sB[2][128 * SA];
    const int tid = threadIdx.x, lane = tid & 31, wid = tid >> 5;
    const int wm = (wid >> 2) * 64, wn = (wid & 3) * 32;
    const int r0 = blockIdx.y * 128, v0 = blockIdx.x * 128;
    const uint32_t saB[2] = {smem_u32(sA[0]), smem_u32(sA[1])};
    const uint32_t sbB[2] = {smem_u32(sB[0]), smem_u32(sB[1])};

    float acc[4][4][4];
#pragma unroll
    for (int mi = 0; mi < 4; mi++)
#pragma unroll
        for (int ni = 0; ni < 4; ni++)
#pragma unroll
            for (int q = 0; q < 4; q++) acc[mi][ni][q] = 0.0f;

    const uint32_t aRow = lane & 15, aK = (lane >> 4) * 8;
    const uint32_t bRow = (lane & 7) + ((lane >> 4) << 3), bK = ((lane >> 3) & 1) * 8;

#define SC_LOAD(buf, kc)                                                      \
    do {                                                                      \
        _Pragma("unroll")                                                     \
        for (int i = 0; i < 2; i++) {                                         \
            const int q = tid + i * 256;                                      \
            const int row = q >> 2, c4 = q & 3;                               \
            cp16(saB[buf] + row * (SA * 2) + c4 * 16,                         \
                 &g_hnb[(size_t)(r0 + row) * HID + (kc) + c4 * 8]);           \
            cp16(sbB[buf] + row * (SA * 2) + c4 * 16,                         \
                 &g_wvb[(size_t)(v0 + row) * HID + (kc) + c4 * 8]);           \
        }                                                                     \
    } while (0)

    SC_LOAD(0, 0); CP_COMMIT();
    for (int ch = 0; ch < 32; ch++) {
        if (ch + 1 < 32) { SC_LOAD((ch + 1) & 1, (ch + 1) * 32); CP_COMMIT(); CP_WAIT1(); }
        else CP_WAIT0();
        __syncthreads();
        const uint32_t sa = saB[ch & 1], sb = sbB[ch & 1];
#pragma unroll
        for (int ks = 0; ks < 2; ks++) {
            uint32_t a[4][4], b[2][4];
#pragma unroll
            for (int mi = 0; mi < 4; mi++)
                ldsm4(a[mi], sa + ((wm + mi * 16 + aRow) * SA + ks * 16 + aK) * 2);
#pragma unroll
            for (int nh = 0; nh < 2; nh++)
                ldsm4(b[nh], sb + ((wn + nh * 16 + bRow) * SA + ks * 16 + bK) * 2);
#pragma unroll
            for (int mi = 0; mi < 4; mi++)
#pragma unroll
                for (int ni = 0; ni < 4; ni++)
                    mmabf16(acc[mi][ni], a[mi], &b[ni >> 1][(ni & 1) * 2]);
        }
        __syncthreads();
    }
    const int mBase = r0 + wm + (lane >> 2);
    const int nOff = 2 * (lane & 3);
#pragma unroll
    for (int mi = 0; mi < 4; mi++) {
#pragma unroll
        for (int ni = 0; ni < 4; ni++) {
            const int v = v0 + wn + ni * 8 + nOff;
            const float bv0 = (v < VOC) ? b_vocab[v] : 0.0f;
            const float bv1 = (v + 1 < VOC) ? b_vocab[v + 1] : 0.0f;
            const int m0 = mBase + mi * 16;
            *(float2*)&g_scores[(size_t)m0 * VOCP + v] =
                make_float2(acc[mi][ni][0] + bv0, acc[mi][ni][1] + bv1);
            *(float2*)&g_scores[(size_t)(m0 + 8) * VOCP + v] =
                make_float2(acc[mi][ni][2] + bv0, acc[mi][ni][3] + bv1);
        }
    }
}

// ---------------- streaming log-softmax NLL ----------------
__global__ void nll_k(const int* __restrict__ captions, float* __restrict__ out) {
    __shared__ float red[256];
    const int r = blockIdx.x, tid = threadIdx.x;
    const int t = r >> 7, n = r & 127;
    const float* row = g_scores + (size_t)r * VOCP;
    float s = 0.0f;
    for (int v = tid; v < VOC; v += 256) s += __expf(row[v]);
    red[tid] = s;
    __syncthreads();
    for (int st = 128; st > 0; st >>= 1) {
        if (tid < st) red[tid] += red[tid + st];
        __syncthreads();
    }
    if (tid == 0) {
        const int tg = captions[n * TCAP + t + 1];
        if (tg != 0) atomicAdd(out, (logf(red[0]) - row[tg]) * (1.0f / (float)NB));
    }
}

// ---------------- launcher ----------------
extern "C" void kernel_launch(void* const* d_in, const int* in_sizes, int n_in,
                              void* d_out, int out_size) {
    const float* features = (const float*)d_in[0];
    const int*   captions = (const int*)  d_in[1];
    const float* W_embed  = (const float*)d_in[2];
    const float* W_proj   = (const float*)d_in[3];
    const float* b_proj   = (const float*)d_in[4];
    const float* Wx       = (const float*)d_in[5];
    const float* Wh       = (const float*)d_in[6];
    const float* Wattn    = (const float*)d_in[7];
    const float* bvec     = (const float*)d_in[8];
    const float* W_vocab  = (const float*)d_in[9];
    const float* b_vocab  = (const float*)d_in[10];
    float* out = (float*)d_out;

    zero_out_k<<<1, 32>>>(out);
    compute_A_k<<<dim3(8, NB), 128>>>(features, W_proj, b_proj);
    conv_we_k<<<(VOC * EMB + 1023) / 1024, 1024>>>(W_embed);
    conv_wxt_k<<<dim3(Z4 / 32, EMB / 32), dim3(32, 8)>>>(Wx);
    conv_wt_k<<<dim3(Z4 / 32, K2 / 32), dim3(32, 8)>>>(Wh, Wattn);
    conv_wv_k<<<dim3(VOCP / 32, HID / 32), dim3(32, 8)>>>(W_vocab);
    embed_mma_k<<<dim3(Z4 / 128, NROWS / 128), 256>>>(captions);
    for (int t = 0; t < TSTEPS; t++) {
        fused_ga_k<<<NB, 512>>>(t);
        step_mma_k<<<64, 256>>>(bvec, t);
    }
    fused_ga_k<<<NB, 512>>>(TSTEPS);   // final gates for t=31
    score_gemm_k<<<dim3(VOCP / 128, NROWS / 128), 256>>>(b_vocab);
    nll_k<<<NROWS, 256>>>(captions, out);
}